// round 6
// baseline (speedup 1.0000x reference)
#include <cuda_runtime.h>
#include <cuda_bf16.h>
#include <math.h>
#include <stdint.h>

// ---------------------------------------------------------------------------
// GCN node classifier, tf32 tensor-core GEMM + CSR gather aggregation.
//   layer: G = rowscale(dinv)*(X @ W);  Y[v] = relu(dinv[v]*(G[v]+sum_{u->v}G[u]) + b)
//   head:  OUT = Y @ Wl + bl
// edge_index is int32.
// Launch order: hist, scan, scatter, gemm1, agg1, gemm2, agg2, head
//   (slot 3 = gemm1 lands in the ncu profiling window next round)
// d_cnt invariant: all-zero before kernel_launch; scan_kernel re-zeroes it
// after use, so every graph replay sees the same state (deterministic).
// ---------------------------------------------------------------------------

#define N_NODES 40000
#define C_FEAT  128
#define N_EDGES 640000

__device__ float d_g[(size_t)N_NODES * C_FEAT];
__device__ float d_y[(size_t)N_NODES * C_FEAT];
__device__ int   d_cnt[N_NODES];        // zero-init at load; re-zeroed by scan
__device__ int   d_off[N_NODES + 1];
__device__ int   d_cursor[N_NODES];
__device__ int   d_adj[N_EDGES];
__device__ float d_dinv[N_NODES];

// ---------------------------------------------------------------------------
// 4 edges per thread via int4 loads of the target list.
__global__ void hist_kernel(const int* __restrict__ ei, int E) {
    int i = blockIdx.x * blockDim.x + threadIdx.x;
    if (i * 4 < E) {
        int4 v = *(const int4*)&ei[E + i * 4];
        atomicAdd(&d_cnt[v.x], 1);
        atomicAdd(&d_cnt[v.y], 1);
        atomicAdd(&d_cnt[v.z], 1);
        atomicAdd(&d_cnt[v.w], 1);
    }
}

// 1024-thread block; warp-shuffle hierarchical exclusive scan over 40000
// counts. Also zeroes d_cnt behind itself (restores pre-launch invariant).
__global__ void scan_kernel() {
    __shared__ int wsum[32];
    const int T = 1024;
    int tid = threadIdx.x;
    int lane = tid & 31, wid = tid >> 5;
    const int per = (N_NODES + T - 1) / T;  // 40
    int s0 = tid * per;
    int s1 = s0 + per; if (s1 > N_NODES) s1 = N_NODES;
    int sum = 0;
    for (int i = s0; i < s1; i++) sum += d_cnt[i];

    int v = sum;
#pragma unroll
    for (int d = 1; d < 32; d <<= 1) {
        int t = __shfl_up_sync(0xffffffffu, v, d);
        if (lane >= d) v += t;
    }
    if (lane == 31) wsum[wid] = v;
    __syncthreads();
    if (wid == 0) {
        int ow = wsum[lane];
        int iv = ow;
#pragma unroll
        for (int d = 1; d < 32; d <<= 1) {
            int t = __shfl_up_sync(0xffffffffu, iv, d);
            if (lane >= d) iv += t;
        }
        wsum[lane] = iv - ow;
    }
    __syncthreads();
    int run = (v - sum) + wsum[wid];
    for (int i = s0; i < s1; i++) {
        int c = d_cnt[i];
        d_cnt[i] = 0;                       // restore invariant for next replay
        d_off[i] = run;
        d_cursor[i] = run;
        d_dinv[i] = rsqrtf((float)(c + 1));
        run += c;
    }
    if (tid == T - 1) d_off[N_NODES] = run;
}

// 4 edges per thread via int4 loads of both source and target lists.
__global__ void scatter_kernel(const int* __restrict__ ei, int E) {
    int i = blockIdx.x * blockDim.x + threadIdx.x;
    if (i * 4 < E) {
        int4 r = *(const int4*)&ei[i * 4];       // sources
        int4 c = *(const int4*)&ei[E + i * 4];   // targets
        d_adj[atomicAdd(&d_cursor[c.x], 1)] = r.x;
        d_adj[atomicAdd(&d_cursor[c.y], 1)] = r.y;
        d_adj[atomicAdd(&d_cursor[c.z], 1)] = r.z;
        d_adj[atomicAdd(&d_cursor[c.w], 1)] = r.w;
    }
}

// ---------------------------------------------------------------------------
// tf32 tensor-core GEMM: C[M,BN] = A[M,128] @ B[128,BN]
// CTA: 128 rows x BN cols, 8 warps. Warp tile: 32 x (BN/2).
// ---------------------------------------------------------------------------
__device__ __forceinline__ uint32_t f2tf(float f) {
    uint32_t r;
    asm("cvt.rna.tf32.f32 %0, %1;" : "=r"(r) : "f"(f));
    return r;
}

template <int BN>
__global__ void __launch_bounds__(256, 2)
gemm_tf32_kernel(const float* __restrict__ Aext,
                 const float* __restrict__ B,
                 const float* __restrict__ bias,
                 float* __restrict__ Cext,
                 int a_sel, int c_sel, int use_rowscale) {
    constexpr int BM = 128, KC = 32, NKC = C_FEAT / KC;
    constexpr int AP = 36;
    constexpr int NP = BN + 4;
    constexpr int WN = BN / 2;
    constexpr int MF = 2;
    constexpr int NF = WN / 8;

    __shared__ uint32_t As[BM * AP];
    __shared__ uint32_t Bs[KC * NP];

    const float* A = (a_sel == 0) ? Aext : (const float*)d_y;
    float*       C = (c_sel == 0) ? Cext : (float*)d_g;

    int tid = threadIdx.x;
    int lane = tid & 31;
    int wid = tid >> 5;
    int warp_m = wid & 3;
    int warp_n = wid >> 2;
    int qid = lane >> 2;
    int qt = lane & 3;
    int row0 = blockIdx.x * BM;

    float acc[MF][NF][4];
#pragma unroll
    for (int i = 0; i < MF; i++)
#pragma unroll
        for (int j = 0; j < NF; j++)
#pragma unroll
            for (int k = 0; k < 4; k++) acc[i][j][k] = 0.f;

    for (int kc = 0; kc < NKC; kc++) {
        int k0 = kc * KC;
        for (int i = tid; i < BM * (KC / 4); i += 256) {
            int r = i >> 3;
            int vv = i & 7;
            int gr = row0 + r; if (gr > N_NODES - 1) gr = N_NODES - 1;
            float4 v = *(const float4*)&A[(size_t)gr * C_FEAT + k0 + vv * 4];
            uint32_t* dst = &As[r * AP + vv * 4];
            dst[0] = f2tf(v.x); dst[1] = f2tf(v.y);
            dst[2] = f2tf(v.z); dst[3] = f2tf(v.w);
        }
        for (int i = tid; i < KC * (BN / 4); i += 256) {
            int r = i / (BN / 4);
            int vv = i % (BN / 4);
            float4 v = *(const float4*)&B[(size_t)(k0 + r) * BN + vv * 4];
            uint32_t* dst = &Bs[r * NP + vv * 4];
            dst[0] = f2tf(v.x); dst[1] = f2tf(v.y);
            dst[2] = f2tf(v.z); dst[3] = f2tf(v.w);
        }
        __syncthreads();

#pragma unroll
        for (int k8 = 0; k8 < KC / 8; k8++) {
            int kb = k8 * 8;
            uint32_t af[MF][4];
#pragma unroll
            for (int im = 0; im < MF; im++) {
                int m0 = warp_m * 32 + im * 16 + qid;
                af[im][0] = As[m0 * AP + kb + qt];
                af[im][1] = As[(m0 + 8) * AP + kb + qt];
                af[im][2] = As[m0 * AP + kb + qt + 4];
                af[im][3] = As[(m0 + 8) * AP + kb + qt + 4];
            }
            uint32_t bf[NF][2];
#pragma unroll
            for (int jn = 0; jn < NF; jn++) {
                int n0 = warp_n * WN + jn * 8 + qid;
                bf[jn][0] = Bs[(kb + qt) * NP + n0];
                bf[jn][1] = Bs[(kb + qt + 4) * NP + n0];
            }
#pragma unroll
            for (int im = 0; im < MF; im++)
#pragma unroll
                for (int jn = 0; jn < NF; jn++) {
                    asm volatile(
                        "mma.sync.aligned.m16n8k8.row.col.f32.tf32.tf32.f32 "
                        "{%0,%1,%2,%3}, {%4,%5,%6,%7}, {%8,%9}, {%0,%1,%2,%3};\n"
                        : "+f"(acc[im][jn][0]), "+f"(acc[im][jn][1]),
                          "+f"(acc[im][jn][2]), "+f"(acc[im][jn][3])
                        : "r"(af[im][0]), "r"(af[im][1]), "r"(af[im][2]), "r"(af[im][3]),
                          "r"(bf[jn][0]), "r"(bf[jn][1]));
                }
        }
        __syncthreads();
    }

#pragma unroll
    for (int im = 0; im < MF; im++) {
        int ra = row0 + warp_m * 32 + im * 16 + qid;
        int rb = ra + 8;
        float sa = 1.f, sb = 1.f;
        if (use_rowscale) {
            if (ra < N_NODES) sa = d_dinv[ra];
            if (rb < N_NODES) sb = d_dinv[rb];
        }
#pragma unroll
        for (int jn = 0; jn < NF; jn++) {
            int col = warp_n * WN + jn * 8 + qt * 2;
            float bx = 0.f, by = 0.f;
            if (bias) { bx = bias[col]; by = bias[col + 1]; }
            if (ra < N_NODES) {
                float2 o = make_float2(fmaf(acc[im][jn][0], sa, bx),
                                       fmaf(acc[im][jn][1], sa, by));
                *(float2*)&C[(size_t)ra * BN + col] = o;
            }
            if (rb < N_NODES) {
                float2 o = make_float2(fmaf(acc[im][jn][2], sb, bx),
                                       fmaf(acc[im][jn][3], sb, by));
                *(float2*)&C[(size_t)rb * BN + col] = o;
            }
        }
    }
}

// ---------------------------------------------------------------------------
// Aggregation: one warp per node, 4 independent accumulators; packed
// add.rn.f32x2 halves the FADD issue count (bit-identical IEEE adds).
// ---------------------------------------------------------------------------
__device__ __forceinline__ void addx2(unsigned long long& a, unsigned long long b) {
    asm("add.rn.f32x2 %0, %1, %2;" : "=l"(a) : "l"(a), "l"(b));
}

__global__ void agg_kernel(const float* __restrict__ bias) {
    int gw = (blockIdx.x * blockDim.x + threadIdx.x) >> 5;
    if (gw >= N_NODES) return;
    int lane = threadIdx.x & 31;
    int c = lane << 2;
    const float* __restrict__ g = (const float*)d_g;

    ulonglong2 s0v = *(const ulonglong2*)&g[(size_t)gw * C_FEAT + c];  // self
    unsigned long long a0 = s0v.x, a1 = s0v.y;
    unsigned long long a2 = 0, a3 = 0, a4 = 0, a5 = 0, a6 = 0, a7 = 0;
    // zero as packed floats: 0ull == {0.f,0.f}

    int s = d_off[gw], e = d_off[gw + 1];
    for (int base = s; base < e; base += 32) {
        int m = e - base; if (m > 32) m = 32;
        int myu = (lane < m) ? d_adj[base + lane] : 0;
        int j = 0;
        for (; j + 4 <= m; j += 4) {
            int u0 = __shfl_sync(0xffffffffu, myu, j);
            int u1 = __shfl_sync(0xffffffffu, myu, j + 1);
            int u2 = __shfl_sync(0xffffffffu, myu, j + 2);
            int u3 = __shfl_sync(0xffffffffu, myu, j + 3);
            ulonglong2 t0 = *(const ulonglong2*)&g[(size_t)u0 * C_FEAT + c];
            ulonglong2 t1 = *(const ulonglong2*)&g[(size_t)u1 * C_FEAT + c];
            ulonglong2 t2 = *(const ulonglong2*)&g[(size_t)u2 * C_FEAT + c];
            ulonglong2 t3 = *(const ulonglong2*)&g[(size_t)u3 * C_FEAT + c];
            addx2(a0, t0.x); addx2(a1, t0.y);
            addx2(a2, t1.x); addx2(a3, t1.y);
            addx2(a4, t2.x); addx2(a5, t2.y);
            addx2(a6, t3.x); addx2(a7, t3.y);
        }
        for (; j < m; j++) {
            int u = __shfl_sync(0xffffffffu, myu, j);
            ulonglong2 t = *(const ulonglong2*)&g[(size_t)u * C_FEAT + c];
            addx2(a0, t.x); addx2(a1, t.y);
        }
    }
    addx2(a0, a2); addx2(a1, a3);
    addx2(a4, a6); addx2(a5, a7);
    addx2(a0, a4); addx2(a1, a5);

    float2 lo = *(float2*)&a0;
    float2 hi = *(float2*)&a1;
    float dv = d_dinv[gw];
    float4 bb = *(const float4*)&bias[c];
    float4 o;
    o.x = fmaxf(fmaf(lo.x, dv, bb.x), 0.f);
    o.y = fmaxf(fmaf(lo.y, dv, bb.y), 0.f);
    o.z = fmaxf(fmaf(hi.x, dv, bb.z), 0.f);
    o.w = fmaxf(fmaf(hi.y, dv, bb.w), 0.f);
    *(float4*)&d_y[(size_t)gw * C_FEAT + c] = o;
}

// ---------------------------------------------------------------------------
extern "C" void kernel_launch(void* const* d_in, const int* in_sizes, int n_in,
                              void* d_out, int out_size) {
    const float* x  = (const float*)d_in[0];
    const int*   ei = (const int*)d_in[1];     // int32
    const float* W1 = (const float*)d_in[2];
    const float* b1 = (const float*)d_in[3];
    const float* W2 = (const float*)d_in[4];
    const float* b2 = (const float*)d_in[5];
    const float* Wl = (const float*)d_in[6];
    const float* bl = (const float*)d_in[7];
    float* out = (float*)d_out;

    int E = in_sizes[1] / 2;   // 640000

    const int gemm_grid = (N_NODES + 127) / 128;        // 313
    const int agg_grid  = (N_NODES * 32 + 255) / 256;   // 5000

    // CSR build (d_cnt is all-zero on entry; scan restores that invariant)
    hist_kernel<<<(E / 4 + 255) / 256, 256>>>(ei, E);        // launch 0
    scan_kernel<<<1, 1024>>>();                              // launch 1
    scatter_kernel<<<(E / 4 + 255) / 256, 256>>>(ei, E);     // launch 2

    // Layer 1  (launch 3 = gemm1 -> lands in ncu's profiling slot)
    gemm_tf32_kernel<128><<<gemm_grid, 256>>>(x, W1, nullptr, nullptr, 0, 1, 1);
    agg_kernel<<<agg_grid, 256>>>(b1);                       // launch 4
    // Layer 2
    gemm_tf32_kernel<128><<<gemm_grid, 256>>>(nullptr, W2, nullptr, nullptr, 1, 1, 1);
    agg_kernel<<<agg_grid, 256>>>(b2);                       // launch 6
    // Head
    gemm_tf32_kernel<64><<<gemm_grid, 256>>>(nullptr, Wl, bl, out, 1, 0, 0);
}

// round 7
// speedup vs baseline: 1.1887x; 1.1887x over previous
#include <cuda_runtime.h>
#include <cuda_bf16.h>
#include <math.h>
#include <stdint.h>

// ---------------------------------------------------------------------------
// GCN node classifier.
//   CSR by destination (+implicit self loop), dinv = rsqrt(deg+1).
//   layer: G = rowscale(dinv)*(X @ W);  Y[v] = relu(dinv[v]*(G[v]+sum G[u]) + b)
//   head:  OUT = Y @ Wl + bl
// GEMM: tf32 mma.sync, cp.async double-buffered raw-fp32 staging,
//       consumer-side cvt.rna. Agg: warp/node float4 gather (R4 form).
// ---------------------------------------------------------------------------

#define N_NODES 40000
#define C_FEAT  128
#define N_EDGES 640000

__device__ float d_g[(size_t)N_NODES * C_FEAT];
__device__ float d_y[(size_t)N_NODES * C_FEAT];
__device__ int   d_cnt[N_NODES];        // zero-init; scan re-zeroes after use
__device__ int   d_off[N_NODES + 1];
__device__ int   d_cursor[N_NODES];
__device__ int   d_adj[N_EDGES];
__device__ float d_dinv[N_NODES];

// ---------------------------------------------------------------------------
__global__ void hist_kernel(const int* __restrict__ ei, int E) {
    int i = blockIdx.x * blockDim.x + threadIdx.x;
    if (i * 4 < E) {
        int4 v = *(const int4*)&ei[E + i * 4];
        atomicAdd(&d_cnt[v.x], 1);
        atomicAdd(&d_cnt[v.y], 1);
        atomicAdd(&d_cnt[v.z], 1);
        atomicAdd(&d_cnt[v.w], 1);
    }
}

__global__ void scan_kernel() {
    __shared__ int wsum[32];
    const int T = 1024;
    int tid = threadIdx.x;
    int lane = tid & 31, wid = tid >> 5;
    const int per = (N_NODES + T - 1) / T;  // 40
    int s0 = tid * per;
    int s1 = s0 + per; if (s1 > N_NODES) s1 = N_NODES;
    int sum = 0;
    for (int i = s0; i < s1; i++) sum += d_cnt[i];

    int v = sum;
#pragma unroll
    for (int d = 1; d < 32; d <<= 1) {
        int t = __shfl_up_sync(0xffffffffu, v, d);
        if (lane >= d) v += t;
    }
    if (lane == 31) wsum[wid] = v;
    __syncthreads();
    if (wid == 0) {
        int ow = wsum[lane];
        int iv = ow;
#pragma unroll
        for (int d = 1; d < 32; d <<= 1) {
            int t = __shfl_up_sync(0xffffffffu, iv, d);
            if (lane >= d) iv += t;
        }
        wsum[lane] = iv - ow;
    }
    __syncthreads();
    int run = (v - sum) + wsum[wid];
    for (int i = s0; i < s1; i++) {
        int c = d_cnt[i];
        d_cnt[i] = 0;                       // restore invariant for next replay
        d_off[i] = run;
        d_cursor[i] = run;
        d_dinv[i] = rsqrtf((float)(c + 1));
        run += c;
    }
    if (tid == T - 1) d_off[N_NODES] = run;
}

__global__ void scatter_kernel(const int* __restrict__ ei, int E) {
    int i = blockIdx.x * blockDim.x + threadIdx.x;
    if (i * 4 < E) {
        int4 r = *(const int4*)&ei[i * 4];       // sources
        int4 c = *(const int4*)&ei[E + i * 4];   // targets
        d_adj[atomicAdd(&d_cursor[c.x], 1)] = r.x;
        d_adj[atomicAdd(&d_cursor[c.y], 1)] = r.y;
        d_adj[atomicAdd(&d_cursor[c.z], 1)] = r.z;
        d_adj[atomicAdd(&d_cursor[c.w], 1)] = r.w;
    }
}

// ---------------------------------------------------------------------------
// tf32 tensor-core GEMM, cp.async 2-stage pipeline.
// C[M,BN] = A[M,128] @ B[128,BN].  CTA: 128 x BN, 8 warps, warp 32 x BN/2.
// ---------------------------------------------------------------------------
__device__ __forceinline__ uint32_t f2tf(float f) {
    uint32_t r;
    asm("cvt.rna.tf32.f32 %0, %1;" : "=r"(r) : "f"(f));
    return r;
}

__device__ __forceinline__ void cp16(uint32_t saddr, const void* gptr) {
    asm volatile("cp.async.ca.shared.global [%0], [%1], 16;\n"
                 :: "r"(saddr), "l"(gptr));
}

template <int BN>
__global__ void __launch_bounds__(256, 2)
gemm_tf32_kernel(const float* __restrict__ Aext,
                 const float* __restrict__ B,
                 const float* __restrict__ bias,
                 float* __restrict__ Cext,
                 int a_sel, int c_sel, int use_rowscale) {
    constexpr int BM = 128, KC = 16, NKC = C_FEAT / KC;   // 8 chunks
    constexpr int AP = 20;            // A smem row stride (words): conflict-free
    constexpr int NP = BN + 8;        // B smem row stride (words): conflict-free
    constexpr int WN = BN / 2;
    constexpr int MF = 2;
    constexpr int NF = WN / 8;
    constexpr int AV = BM * KC / 4;   // A float4s per chunk: 512
    constexpr int BV = KC * BN / 4;   // B float4s per chunk: 512 / 256

    __shared__ float As[2][BM * AP];
    __shared__ float Bs[2][KC * NP];

    const float* A = (a_sel == 0) ? Aext : (const float*)d_y;
    float*       C = (c_sel == 0) ? Cext : (float*)d_g;

    int tid = threadIdx.x;
    int lane = tid & 31;
    int wid = tid >> 5;
    int warp_m = wid & 3;
    int warp_n = wid >> 2;
    int qid = lane >> 2;
    int qt = lane & 3;
    int row0 = blockIdx.x * BM;

    uint32_t a_smem[2], b_smem[2];
#pragma unroll
    for (int s = 0; s < 2; s++) {
        a_smem[s] = (uint32_t)__cvta_generic_to_shared(&As[s][0]);
        b_smem[s] = (uint32_t)__cvta_generic_to_shared(&Bs[s][0]);
    }

    // producer: issue cp.asyncs for chunk kc into stage st
    auto load_chunk = [&](int kc, int st) {
        int k0 = kc * KC;
#pragma unroll
        for (int i = 0; i < AV / 256; i++) {
            int idx = tid + i * 256;
            int r = idx >> 2, vv = idx & 3;
            int gr = row0 + r; if (gr >= N_NODES) gr = N_NODES - 1;
            cp16(a_smem[st] + (r * AP + vv * 4) * 4,
                 &A[(size_t)gr * C_FEAT + k0 + vv * 4]);
        }
#pragma unroll
        for (int i = 0; i < (BV + 255) / 256; i++) {
            int idx = tid + i * 256;
            if (BV % 256 == 0 || idx < BV) {
                int r = idx / (BN / 4), vv = idx % (BN / 4);
                cp16(b_smem[st] + (r * NP + vv * 4) * 4,
                     &B[(size_t)(k0 + r) * BN + vv * 4]);
            }
        }
        asm volatile("cp.async.commit_group;" ::: "memory");
    };

    float acc[MF][NF][4];
#pragma unroll
    for (int i = 0; i < MF; i++)
#pragma unroll
        for (int j = 0; j < NF; j++)
#pragma unroll
            for (int k = 0; k < 4; k++) acc[i][j][k] = 0.f;

    load_chunk(0, 0);

    for (int kc = 0; kc < NKC; kc++) {
        int st = kc & 1;
        if (kc + 1 < NKC) {
            load_chunk(kc + 1, st ^ 1);
            asm volatile("cp.async.wait_group 1;" ::: "memory");
        } else {
            asm volatile("cp.async.wait_group 0;" ::: "memory");
        }
        __syncthreads();

        const float* __restrict__ Asb = As[st];
        const float* __restrict__ Bsb = Bs[st];
#pragma unroll
        for (int k8 = 0; k8 < KC / 8; k8++) {
            int kb = k8 * 8;
            uint32_t af[MF][4];
#pragma unroll
            for (int im = 0; im < MF; im++) {
                int m0 = warp_m * 32 + im * 16 + qid;
                af[im][0] = f2tf(Asb[m0 * AP + kb + qt]);
                af[im][1] = f2tf(Asb[(m0 + 8) * AP + kb + qt]);
                af[im][2] = f2tf(Asb[m0 * AP + kb + qt + 4]);
                af[im][3] = f2tf(Asb[(m0 + 8) * AP + kb + qt + 4]);
            }
            uint32_t bf[NF][2];
#pragma unroll
            for (int jn = 0; jn < NF; jn++) {
                int n0 = warp_n * WN + jn * 8 + qid;
                bf[jn][0] = f2tf(Bsb[(kb + qt) * NP + n0]);
                bf[jn][1] = f2tf(Bsb[(kb + qt + 4) * NP + n0]);
            }
#pragma unroll
            for (int im = 0; im < MF; im++)
#pragma unroll
                for (int jn = 0; jn < NF; jn++) {
                    asm volatile(
                        "mma.sync.aligned.m16n8k8.row.col.f32.tf32.tf32.f32 "
                        "{%0,%1,%2,%3}, {%4,%5,%6,%7}, {%8,%9}, {%0,%1,%2,%3};\n"
                        : "+f"(acc[im][jn][0]), "+f"(acc[im][jn][1]),
                          "+f"(acc[im][jn][2]), "+f"(acc[im][jn][3])
                        : "r"(af[im][0]), "r"(af[im][1]), "r"(af[im][2]), "r"(af[im][3]),
                          "r"(bf[jn][0]), "r"(bf[jn][1]));
                }
        }
        __syncthreads();
    }

#pragma unroll
    for (int im = 0; im < MF; im++) {
        int ra = row0 + warp_m * 32 + im * 16 + qid;
        int rb = ra + 8;
        float sa = 1.f, sb = 1.f;
        if (use_rowscale) {
            if (ra < N_NODES) sa = d_dinv[ra];
            if (rb < N_NODES) sb = d_dinv[rb];
        }
#pragma unroll
        for (int jn = 0; jn < NF; jn++) {
            int col = warp_n * WN + jn * 8 + qt * 2;
            float bx = 0.f, by = 0.f;
            if (bias) { bx = bias[col]; by = bias[col + 1]; }
            if (ra < N_NODES) {
                float2 o = make_float2(fmaf(acc[im][jn][0], sa, bx),
                                       fmaf(acc[im][jn][1], sa, by));
                *(float2*)&C[(size_t)ra * BN + col] = o;
            }
            if (rb < N_NODES) {
                float2 o = make_float2(fmaf(acc[im][jn][2], sb, bx),
                                       fmaf(acc[im][jn][3], sb, by));
                *(float2*)&C[(size_t)rb * BN + col] = o;
            }
        }
    }
}

// ---------------------------------------------------------------------------
// Aggregation (R4 form): one warp per node, 4 independent float4 accumulators.
// ---------------------------------------------------------------------------
__global__ void agg_kernel(const float* __restrict__ bias) {
    int gw = (blockIdx.x * blockDim.x + threadIdx.x) >> 5;
    if (gw >= N_NODES) return;
    int lane = threadIdx.x & 31;
    int c = lane << 2;
    const float* __restrict__ g = (const float*)d_g;

    float4 a0 = *(const float4*)&g[(size_t)gw * C_FEAT + c];  // self loop
    float4 a1 = make_float4(0.f, 0.f, 0.f, 0.f);
    float4 a2 = a1, a3 = a1;

    int s = d_off[gw], e = d_off[gw + 1];
    for (int base = s; base < e; base += 32) {
        int m = e - base; if (m > 32) m = 32;
        int myu = (lane < m) ? d_adj[base + lane] : 0;
        int j = 0;
        for (; j + 4 <= m; j += 4) {
            int u0 = __shfl_sync(0xffffffffu, myu, j);
            int u1 = __shfl_sync(0xffffffffu, myu, j + 1);
            int u2 = __shfl_sync(0xffffffffu, myu, j + 2);
            int u3 = __shfl_sync(0xffffffffu, myu, j + 3);
            float4 t0 = *(const float4*)&g[(size_t)u0 * C_FEAT + c];
            float4 t1 = *(const float4*)&g[(size_t)u1 * C_FEAT + c];
            float4 t2 = *(const float4*)&g[(size_t)u2 * C_FEAT + c];
            float4 t3 = *(const float4*)&g[(size_t)u3 * C_FEAT + c];
            a0.x += t0.x; a0.y += t0.y; a0.z += t0.z; a0.w += t0.w;
            a1.x += t1.x; a1.y += t1.y; a1.z += t1.z; a1.w += t1.w;
            a2.x += t2.x; a2.y += t2.y; a2.z += t2.z; a2.w += t2.w;
            a3.x += t3.x; a3.y += t3.y; a3.z += t3.z; a3.w += t3.w;
        }
        for (; j < m; j++) {
            int u = __shfl_sync(0xffffffffu, myu, j);
            float4 t = *(const float4*)&g[(size_t)u * C_FEAT + c];
            a0.x += t.x; a0.y += t.y; a0.z += t.z; a0.w += t.w;
        }
    }
    float4 acc = make_float4(a0.x + a1.x + a2.x + a3.x,
                             a0.y + a1.y + a2.y + a3.y,
                             a0.z + a1.z + a2.z + a3.z,
                             a0.w + a1.w + a2.w + a3.w);
    float dv = d_dinv[gw];
    float4 bb = *(const float4*)&bias[c];
    float4 o;
    o.x = fmaxf(fmaf(acc.x, dv, bb.x), 0.f);
    o.y = fmaxf(fmaf(acc.y, dv, bb.y), 0.f);
    o.z = fmaxf(fmaf(acc.z, dv, bb.z), 0.f);
    o.w = fmaxf(fmaf(acc.w, dv, bb.w), 0.f);
    *(float4*)&d_y[(size_t)gw * C_FEAT + c] = o;
}

// ---------------------------------------------------------------------------
extern "C" void kernel_launch(void* const* d_in, const int* in_sizes, int n_in,
                              void* d_out, int out_size) {
    const float* x  = (const float*)d_in[0];
    const int*   ei = (const int*)d_in[1];     // int32
    const float* W1 = (const float*)d_in[2];
    const float* b1 = (const float*)d_in[3];
    const float* W2 = (const float*)d_in[4];
    const float* b2 = (const float*)d_in[5];
    const float* Wl = (const float*)d_in[6];
    const float* bl = (const float*)d_in[7];
    float* out = (float*)d_out;

    int E = in_sizes[1] / 2;   // 640000

    const int gemm_grid = (N_NODES + 127) / 128;        // 313
    const int agg_grid  = (N_NODES * 32 + 255) / 256;   // 5000

    // CSR build
    hist_kernel<<<(E / 4 + 255) / 256, 256>>>(ei, E);        // 0
    scan_kernel<<<1, 1024>>>();                              // 1
    scatter_kernel<<<(E / 4 + 255) / 256, 256>>>(ei, E);     // 2

    // Layer 1 (launch 3 = gemm1 -> ncu slot: validates cp.async pipeline)
    gemm_tf32_kernel<128><<<gemm_grid, 256>>>(x, W1, nullptr, nullptr, 0, 1, 1);
    agg_kernel<<<agg_grid, 256>>>(b1);                       // 4
    // Layer 2
    gemm_tf32_kernel<128><<<gemm_grid, 256>>>(nullptr, W2, nullptr, nullptr, 1, 1, 1);
    agg_kernel<<<agg_grid, 256>>>(b2);                       // 6
    // Head
    gemm_tf32_kernel<64><<<gemm_grid, 256>>>(nullptr, Wl, bl, out, 1, 0, 0);
}

// round 10
// speedup vs baseline: 1.7493x; 1.4716x over previous
#include <cuda_runtime.h>
#include <cuda_bf16.h>
#include <math.h>
#include <stdint.h>

// ---------------------------------------------------------------------------
// GCN node classifier.
//   CSR by destination (+implicit self loop), dinv = rsqrt(deg+1).
//   layer: G = rowscale(dinv)*(X @ W);  Y[v] = relu(dinv[v]*(G[v]+sum G[u]) + b)
//   head:  OUT = Y @ Wl + bl
// GEMM: tf32 mma.sync, cp.async double-buffered. Agg: warp/node float4 gather.
// Scan: single block, COALESCED tiled layout (tile t, element t*1024+tid) —
//   the previous thread-contiguous layout was stride-160B = 32 wavefronts per
//   access on one SM (~100us hidden cost).
// ---------------------------------------------------------------------------

#define N_NODES 40000
#define C_FEAT  128
#define N_EDGES 640000

__device__ float d_g[(size_t)N_NODES * C_FEAT];
__device__ float d_y[(size_t)N_NODES * C_FEAT];
__device__ int   d_cnt[N_NODES];        // zero-init; scan re-zeroes after use
__device__ int   d_off[N_NODES + 1];
__device__ int   d_cursor[N_NODES];
__device__ int   d_adj[N_EDGES];
__device__ float d_dinv[N_NODES];

// ---------------------------------------------------------------------------
__global__ void hist_kernel(const int* __restrict__ ei, int E) {
    int i = blockIdx.x * blockDim.x + threadIdx.x;
    if (i * 4 < E) {
        int4 v = *(const int4*)&ei[E + i * 4];
        atomicAdd(&d_cnt[v.x], 1);
        atomicAdd(&d_cnt[v.y], 1);
        atomicAdd(&d_cnt[v.z], 1);
        atomicAdd(&d_cnt[v.w], 1);
    }
}

// Single 1024-thread block; 40 coalesced tiles, register carry.
__global__ void scan_kernel() {
    __shared__ int wred[33];   // [0..31] warp offsets, [32] tile total
    const int NT = (N_NODES + 1023) / 1024;   // 40 tiles
    int tid = threadIdx.x, lane = tid & 31, wid = tid >> 5;
    int carry = 0;

    for (int t = 0; t < NT; t++) {
        int i = t * 1024 + tid;
        int c = (i < N_NODES) ? d_cnt[i] : 0;
        // warp inclusive scan
        int v = c;
#pragma unroll
        for (int d = 1; d < 32; d <<= 1) {
            int u = __shfl_up_sync(0xffffffffu, v, d);
            if (lane >= d) v += u;
        }
        __syncthreads();                  // protect wred from prior tile readers
        if (lane == 31) wred[wid] = v;
        __syncthreads();
        if (wid == 0) {
            int wv = wred[lane];
            int iv = wv;
#pragma unroll
            for (int d = 1; d < 32; d <<= 1) {
                int u = __shfl_up_sync(0xffffffffu, iv, d);
                if (lane >= d) iv += u;
            }
            wred[lane] = iv - wv;         // exclusive warp offset
            if (lane == 31) wred[32] = iv;  // tile total
        }
        __syncthreads();
        int pos = carry + wred[wid] + (v - c);   // block-exclusive + carry
        if (i < N_NODES) {
            d_off[i] = pos;
            d_cursor[i] = pos;
            d_dinv[i] = rsqrtf((float)(c + 1));
            d_cnt[i] = 0;                 // restore invariant for next replay
        }
        carry += wred[32];
    }
    if (tid == 0) d_off[N_NODES] = carry;
}

__global__ void scatter_kernel(const int* __restrict__ ei, int E) {
    int i = blockIdx.x * blockDim.x + threadIdx.x;
    if (i * 4 < E) {
        int4 r = *(const int4*)&ei[i * 4];       // sources
        int4 c = *(const int4*)&ei[E + i * 4];   // targets
        d_adj[atomicAdd(&d_cursor[c.x], 1)] = r.x;
        d_adj[atomicAdd(&d_cursor[c.y], 1)] = r.y;
        d_adj[atomicAdd(&d_cursor[c.z], 1)] = r.z;
        d_adj[atomicAdd(&d_cursor[c.w], 1)] = r.w;
    }
}

// ---------------------------------------------------------------------------
// tf32 tensor-core GEMM, cp.async 2-stage pipeline.
// C[M,BN] = A[M,128] @ B[128,BN].  CTA: 128 x BN, 8 warps, warp 32 x BN/2.
// ---------------------------------------------------------------------------
__device__ __forceinline__ uint32_t f2tf(float f) {
    uint32_t r;
    asm("cvt.rna.tf32.f32 %0, %1;" : "=r"(r) : "f"(f));
    return r;
}

__device__ __forceinline__ void cp16(uint32_t saddr, const void* gptr) {
    asm volatile("cp.async.ca.shared.global [%0], [%1], 16;\n"
                 :: "r"(saddr), "l"(gptr));
}

template <int BN>
__global__ void __launch_bounds__(256, 2)
gemm_tf32_kernel(const float* __restrict__ Aext,
                 const float* __restrict__ B,
                 const float* __restrict__ bias,
                 float* __restrict__ Cext,
                 int a_sel, int c_sel, int use_rowscale) {
    constexpr int BM = 128, KC = 16, NKC = C_FEAT / KC;   // 8 chunks
    constexpr int AP = 20;
    constexpr int NP = BN + 8;
    constexpr int WN = BN / 2;
    constexpr int MF = 2;
    constexpr int NF = WN / 8;
    constexpr int AV = BM * KC / 4;
    constexpr int BV = KC * BN / 4;

    __shared__ float As[2][BM * AP];
    __shared__ float Bs[2][KC * NP];

    const float* A = (a_sel == 0) ? Aext : (const float*)d_y;
    float*       C = (c_sel == 0) ? Cext : (float*)d_g;

    int tid = threadIdx.x;
    int lane = tid & 31;
    int wid = tid >> 5;
    int warp_m = wid & 3;
    int warp_n = wid >> 2;
    int qid = lane >> 2;
    int qt = lane & 3;
    int row0 = blockIdx.x * BM;

    uint32_t a_smem[2], b_smem[2];
#pragma unroll
    for (int s = 0; s < 2; s++) {
        a_smem[s] = (uint32_t)__cvta_generic_to_shared(&As[s][0]);
        b_smem[s] = (uint32_t)__cvta_generic_to_shared(&Bs[s][0]);
    }

    auto load_chunk = [&](int kc, int st) {
        int k0 = kc * KC;
#pragma unroll
        for (int i = 0; i < AV / 256; i++) {
            int idx = tid + i * 256;
            int r = idx >> 2, vv = idx & 3;
            int gr = row0 + r; if (gr >= N_NODES) gr = N_NODES - 1;
            cp16(a_smem[st] + (r * AP + vv * 4) * 4,
                 &A[(size_t)gr * C_FEAT + k0 + vv * 4]);
        }
#pragma unroll
        for (int i = 0; i < (BV + 255) / 256; i++) {
            int idx = tid + i * 256;
            if (BV % 256 == 0 || idx < BV) {
                int r = idx / (BN / 4), vv = idx % (BN / 4);
                cp16(b_smem[st] + (r * NP + vv * 4) * 4,
                     &B[(size_t)(k0 + r) * BN + vv * 4]);
            }
        }
        asm volatile("cp.async.commit_group;" ::: "memory");
    };

    float acc[MF][NF][4];
#pragma unroll
    for (int i = 0; i < MF; i++)
#pragma unroll
        for (int j = 0; j < NF; j++)
#pragma unroll
            for (int k = 0; k < 4; k++) acc[i][j][k] = 0.f;

    load_chunk(0, 0);

    for (int kc = 0; kc < NKC; kc++) {
        int st = kc & 1;
        if (kc + 1 < NKC) {
            load_chunk(kc + 1, st ^ 1);
            asm volatile("cp.async.wait_group 1;" ::: "memory");
        } else {
            asm volatile("cp.async.wait_group 0;" ::: "memory");
        }
        __syncthreads();

        const float* __restrict__ Asb = As[st];
        const float* __restrict__ Bsb = Bs[st];
#pragma unroll
        for (int k8 = 0; k8 < KC / 8; k8++) {
            int kb = k8 * 8;
            uint32_t af[MF][4];
#pragma unroll
            for (int im = 0; im < MF; im++) {
                int m0 = warp_m * 32 + im * 16 + qid;
                af[im][0] = f2tf(Asb[m0 * AP + kb + qt]);
                af[im][1] = f2tf(Asb[(m0 + 8) * AP + kb + qt]);
                af[im][2] = f2tf(Asb[m0 * AP + kb + qt + 4]);
                af[im][3] = f2tf(Asb[(m0 + 8) * AP + kb + qt + 4]);
            }
            uint32_t bf[NF][2];
#pragma unroll
            for (int jn = 0; jn < NF; jn++) {
                int n0 = warp_n * WN + jn * 8 + qid;
                bf[jn][0] = f2tf(Bsb[(kb + qt) * NP + n0]);
                bf[jn][1] = f2tf(Bsb[(kb + qt + 4) * NP + n0]);
            }
#pragma unroll
            for (int im = 0; im < MF; im++)
#pragma unroll
                for (int jn = 0; jn < NF; jn++) {
                    asm volatile(
                        "mma.sync.aligned.m16n8k8.row.col.f32.tf32.tf32.f32 "
                        "{%0,%1,%2,%3}, {%4,%5,%6,%7}, {%8,%9}, {%0,%1,%2,%3};\n"
                        : "+f"(acc[im][jn][0]), "+f"(acc[im][jn][1]),
                          "+f"(acc[im][jn][2]), "+f"(acc[im][jn][3])
                        : "r"(af[im][0]), "r"(af[im][1]), "r"(af[im][2]), "r"(af[im][3]),
                          "r"(bf[jn][0]), "r"(bf[jn][1]));
                }
        }
        __syncthreads();
    }

#pragma unroll
    for (int im = 0; im < MF; im++) {
        int ra = row0 + warp_m * 32 + im * 16 + qid;
        int rb = ra + 8;
        float sa = 1.f, sb = 1.f;
        if (use_rowscale) {
            if (ra < N_NODES) sa = d_dinv[ra];
            if (rb < N_NODES) sb = d_dinv[rb];
        }
#pragma unroll
        for (int jn = 0; jn < NF; jn++) {
            int col = warp_n * WN + jn * 8 + qt * 2;
            float bx = 0.f, by = 0.f;
            if (bias) { bx = bias[col]; by = bias[col + 1]; }
            if (ra < N_NODES) {
                float2 o = make_float2(fmaf(acc[im][jn][0], sa, bx),
                                       fmaf(acc[im][jn][1], sa, by));
                *(float2*)&C[(size_t)ra * BN + col] = o;
            }
            if (rb < N_NODES) {
                float2 o = make_float2(fmaf(acc[im][jn][2], sb, bx),
                                       fmaf(acc[im][jn][3], sb, by));
                *(float2*)&C[(size_t)rb * BN + col] = o;
            }
        }
    }
}

// ---------------------------------------------------------------------------
// Aggregation: one warp per node, 4 independent float4 accumulators.
// ---------------------------------------------------------------------------
__global__ void agg_kernel(const float* __restrict__ bias) {
    int gw = (blockIdx.x * blockDim.x + threadIdx.x) >> 5;
    if (gw >= N_NODES) return;
    int lane = threadIdx.x & 31;
    int c = lane << 2;
    const float* __restrict__ g = (const float*)d_g;

    float4 a0 = *(const float4*)&g[(size_t)gw * C_FEAT + c];  // self loop
    float4 a1 = make_float4(0.f, 0.f, 0.f, 0.f);
    float4 a2 = a1, a3 = a1;

    int s = d_off[gw], e = d_off[gw + 1];
    for (int base = s; base < e; base += 32) {
        int m = e - base; if (m > 32) m = 32;
        int myu = (lane < m) ? d_adj[base + lane] : 0;
        int j = 0;
        for (; j + 4 <= m; j += 4) {
            int u0 = __shfl_sync(0xffffffffu, myu, j);
            int u1 = __shfl_sync(0xffffffffu, myu, j + 1);
            int u2 = __shfl_sync(0xffffffffu, myu, j + 2);
            int u3 = __shfl_sync(0xffffffffu, myu, j + 3);
            float4 t0 = *(const float4*)&g[(size_t)u0 * C_FEAT + c];
            float4 t1 = *(const float4*)&g[(size_t)u1 * C_FEAT + c];
            float4 t2 = *(const float4*)&g[(size_t)u2 * C_FEAT + c];
            float4 t3 = *(const float4*)&g[(size_t)u3 * C_FEAT + c];
            a0.x += t0.x; a0.y += t0.y; a0.z += t0.z; a0.w += t0.w;
            a1.x += t1.x; a1.y += t1.y; a1.z += t1.z; a1.w += t1.w;
            a2.x += t2.x; a2.y += t2.y; a2.z += t2.z; a2.w += t2.w;
            a3.x += t3.x; a3.y += t3.y; a3.z += t3.z; a3.w += t3.w;
        }
        for (; j < m; j++) {
            int u = __shfl_sync(0xffffffffu, myu, j);
            float4 t = *(const float4*)&g[(size_t)u * C_FEAT + c];
            a0.x += t.x; a0.y += t.y; a0.z += t.z; a0.w += t.w;
        }
    }
    float4 acc = make_float4(a0.x + a1.x + a2.x + a3.x,
                             a0.y + a1.y + a2.y + a3.y,
                             a0.z + a1.z + a2.z + a3.z,
                             a0.w + a1.w + a2.w + a3.w);
    float dv = d_dinv[gw];
    float4 bb = *(const float4*)&bias[c];
    float4 o;
    o.x = fmaxf(fmaf(acc.x, dv, bb.x), 0.f);
    o.y = fmaxf(fmaf(acc.y, dv, bb.y), 0.f);
    o.z = fmaxf(fmaf(acc.z, dv, bb.z), 0.f);
    o.w = fmaxf(fmaf(acc.w, dv, bb.w), 0.f);
    *(float4*)&d_y[(size_t)gw * C_FEAT + c] = o;
}

// ---------------------------------------------------------------------------
extern "C" void kernel_launch(void* const* d_in, const int* in_sizes, int n_in,
                              void* d_out, int out_size) {
    const float* x  = (const float*)d_in[0];
    const int*   ei = (const int*)d_in[1];     // int32
    const float* W1 = (const float*)d_in[2];
    const float* b1 = (const float*)d_in[3];
    const float* W2 = (const float*)d_in[4];
    const float* b2 = (const float*)d_in[5];
    const float* Wl = (const float*)d_in[6];
    const float* bl = (const float*)d_in[7];
    float* out = (float*)d_out;

    int E = in_sizes[1] / 2;   // 640000

    const int gemm_grid = (N_NODES + 127) / 128;        // 313
    const int agg_grid  = (N_NODES * 32 + 255) / 256;   // 5000

    // CSR build
    hist_kernel<<<(E / 4 + 255) / 256, 256>>>(ei, E);        // 0
    scan_kernel<<<1, 1024>>>();                              // 1
    scatter_kernel<<<(E / 4 + 255) / 256, 256>>>(ei, E);     // 2

    // Layer 1 (launch 3 = gemm1 -> ncu slot)
    gemm_tf32_kernel<128><<<gemm_grid, 256>>>(x, W1, nullptr, nullptr, 0, 1, 1);
    agg_kernel<<<agg_grid, 256>>>(b1);                       // 4
    // Layer 2
    gemm_tf32_kernel<128><<<gemm_grid, 256>>>(nullptr, W2, nullptr, nullptr, 1, 1, 1);
    agg_kernel<<<agg_grid, 256>>>(b2);                       // 6
    // Head
    gemm_tf32_kernel<64><<<gemm_grid, 256>>>(nullptr, Wl, bl, out, 1, 0, 0);
}

// round 11
// speedup vs baseline: 1.8039x; 1.0312x over previous
#include <cuda_runtime.h>
#include <cuda_bf16.h>
#include <math.h>
#include <stdint.h>

// ---------------------------------------------------------------------------
// GCN node classifier.
//   CSR by destination (+implicit self loop), dinv = rsqrt(deg+1).
//   layer: G = rowscale(dinv)*(X @ W);  Y[v] = relu(dinv[v]*(G[v]+sum G[u]) + b)
//   head:  OUT = Y @ Wl + bl
// GEMM: tf32 mma.sync, cp.async 2-stage, BM=64 tile / 3 CTAs-per-SM for
//   latency hiding (R10 profile: occ 21.6%, issue 33.6% -> occupancy-bound).
// Agg: warp/node float4 gather (near LTS roofline, ~31us/layer).
// Scan: coalesced single-block tiled scan (R10 win).
// ---------------------------------------------------------------------------

#define N_NODES 40000
#define C_FEAT  128
#define N_EDGES 640000

__device__ float d_g[(size_t)N_NODES * C_FEAT];
__device__ float d_y[(size_t)N_NODES * C_FEAT];
__device__ int   d_cnt[N_NODES];        // zero-init; scan re-zeroes after use
__device__ int   d_off[N_NODES + 1];
__device__ int   d_cursor[N_NODES];
__device__ int   d_adj[N_EDGES];
__device__ float d_dinv[N_NODES];

// ---------------------------------------------------------------------------
__global__ void hist_kernel(const int* __restrict__ ei, int E) {
    int i = blockIdx.x * blockDim.x + threadIdx.x;
    if (i * 4 < E) {
        int4 v = *(const int4*)&ei[E + i * 4];
        atomicAdd(&d_cnt[v.x], 1);
        atomicAdd(&d_cnt[v.y], 1);
        atomicAdd(&d_cnt[v.z], 1);
        atomicAdd(&d_cnt[v.w], 1);
    }
}

// Single 1024-thread block; 40 coalesced tiles, register carry.
__global__ void scan_kernel() {
    __shared__ int wred[33];   // [0..31] warp offsets, [32] tile total
    const int NT = (N_NODES + 1023) / 1024;   // 40 tiles
    int tid = threadIdx.x, lane = tid & 31, wid = tid >> 5;
    int carry = 0;

    for (int t = 0; t < NT; t++) {
        int i = t * 1024 + tid;
        int c = (i < N_NODES) ? d_cnt[i] : 0;
        int v = c;
#pragma unroll
        for (int d = 1; d < 32; d <<= 1) {
            int u = __shfl_up_sync(0xffffffffu, v, d);
            if (lane >= d) v += u;
        }
        __syncthreads();
        if (lane == 31) wred[wid] = v;
        __syncthreads();
        if (wid == 0) {
            int wv = wred[lane];
            int iv = wv;
#pragma unroll
            for (int d = 1; d < 32; d <<= 1) {
                int u = __shfl_up_sync(0xffffffffu, iv, d);
                if (lane >= d) iv += u;
            }
            wred[lane] = iv - wv;
            if (lane == 31) wred[32] = iv;
        }
        __syncthreads();
        int pos = carry + wred[wid] + (v - c);
        if (i < N_NODES) {
            d_off[i] = pos;
            d_cursor[i] = pos;
            d_dinv[i] = rsqrtf((float)(c + 1));
            d_cnt[i] = 0;                 // restore invariant for next replay
        }
        carry += wred[32];
    }
    if (tid == 0) d_off[N_NODES] = carry;
}

__global__ void scatter_kernel(const int* __restrict__ ei, int E) {
    int i = blockIdx.x * blockDim.x + threadIdx.x;
    if (i * 4 < E) {
        int4 r = *(const int4*)&ei[i * 4];       // sources
        int4 c = *(const int4*)&ei[E + i * 4];   // targets
        d_adj[atomicAdd(&d_cursor[c.x], 1)] = r.x;
        d_adj[atomicAdd(&d_cursor[c.y], 1)] = r.y;
        d_adj[atomicAdd(&d_cursor[c.z], 1)] = r.z;
        d_adj[atomicAdd(&d_cursor[c.w], 1)] = r.w;
    }
}

// ---------------------------------------------------------------------------
// tf32 tensor-core GEMM, cp.async 2-stage pipeline.
// C[M,BN] = A[M,128] @ B[128,BN].  CTA: 64 x BN, 8 warps (2x4),
// warp tile 32 x (BN/4).  3 CTAs/SM for latency hiding.
// ---------------------------------------------------------------------------
__device__ __forceinline__ uint32_t f2tf(float f) {
    uint32_t r;
    asm("cvt.rna.tf32.f32 %0, %1;" : "=r"(r) : "f"(f));
    return r;
}

__device__ __forceinline__ void cp16(uint32_t saddr, const void* gptr) {
    asm volatile("cp.async.ca.shared.global [%0], [%1], 16;\n"
                 :: "r"(saddr), "l"(gptr));
}

template <int BN>
__global__ void __launch_bounds__(256, 3)
gemm_tf32_kernel(const float* __restrict__ Aext,
                 const float* __restrict__ B,
                 const float* __restrict__ bias,
                 float* __restrict__ Cext,
                 int a_sel, int c_sel, int use_rowscale) {
    constexpr int BM = 64, KC = 16, NKC = C_FEAT / KC;   // 8 chunks
    constexpr int AP = 20;            // A smem row stride (words)
    constexpr int NP = BN + 8;        // B smem row stride (words)
    constexpr int WN = BN / 4;        // warp n extent (32 or 16)
    constexpr int MF = 2;             // 32 rows / 16
    constexpr int NF = WN / 8;        // 4 (BN=128) or 2 (BN=64)
    constexpr int AV = BM * KC / 4;   // 256 float4 per A chunk
    constexpr int BV = KC * BN / 4;   // 512 / 256 float4 per B chunk

    __shared__ float As[2][BM * AP];
    __shared__ float Bs[2][KC * NP];

    const float* A = (a_sel == 0) ? Aext : (const float*)d_y;
    float*       C = (c_sel == 0) ? Cext : (float*)d_g;

    int tid = threadIdx.x;
    int lane = tid & 31;
    int wid = tid >> 5;
    int warp_m = wid & 1;             // 0..1
    int warp_n = wid >> 1;            // 0..3
    int qid = lane >> 2;              // 0..7
    int qt = lane & 3;                // 0..3
    int row0 = blockIdx.x * BM;

    uint32_t a_smem[2], b_smem[2];
#pragma unroll
    for (int s = 0; s < 2; s++) {
        a_smem[s] = (uint32_t)__cvta_generic_to_shared(&As[s][0]);
        b_smem[s] = (uint32_t)__cvta_generic_to_shared(&Bs[s][0]);
    }

    auto load_chunk = [&](int kc, int st) {
        int k0 = kc * KC;
        {   // A: 256 float4s, one pass of 256 threads
            int r = tid >> 2, vv = tid & 3;
            int gr = row0 + r; if (gr >= N_NODES) gr = N_NODES - 1;
            cp16(a_smem[st] + (r * AP + vv * 4) * 4,
                 &A[(size_t)gr * C_FEAT + k0 + vv * 4]);
        }
#pragma unroll
        for (int i = 0; i < BV / 256; i++) {
            int idx = tid + i * 256;
            int r = idx / (BN / 4), vv = idx % (BN / 4);
            cp16(b_smem[st] + (r * NP + vv * 4) * 4,
                 &B[(size_t)(k0 + r) * BN + vv * 4]);
        }
        asm volatile("cp.async.commit_group;" ::: "memory");
    };

    float acc[MF][NF][4];
#pragma unroll
    for (int i = 0; i < MF; i++)
#pragma unroll
        for (int j = 0; j < NF; j++)
#pragma unroll
            for (int k = 0; k < 4; k++) acc[i][j][k] = 0.f;

    load_chunk(0, 0);

    for (int kc = 0; kc < NKC; kc++) {
        int st = kc & 1;
        if (kc + 1 < NKC) {
            load_chunk(kc + 1, st ^ 1);
            asm volatile("cp.async.wait_group 1;" ::: "memory");
        } else {
            asm volatile("cp.async.wait_group 0;" ::: "memory");
        }
        __syncthreads();

        const float* __restrict__ Asb = As[st];
        const float* __restrict__ Bsb = Bs[st];
#pragma unroll
        for (int k8 = 0; k8 < KC / 8; k8++) {
            int kb = k8 * 8;
            uint32_t af[MF][4];
#pragma unroll
            for (int im = 0; im < MF; im++) {
                int m0 = warp_m * 32 + im * 16 + qid;
                af[im][0] = f2tf(Asb[m0 * AP + kb + qt]);
                af[im][1] = f2tf(Asb[(m0 + 8) * AP + kb + qt]);
                af[im][2] = f2tf(Asb[m0 * AP + kb + qt + 4]);
                af[im][3] = f2tf(Asb[(m0 + 8) * AP + kb + qt + 4]);
            }
            uint32_t bf[NF][2];
#pragma unroll
            for (int jn = 0; jn < NF; jn++) {
                int n0 = warp_n * WN + jn * 8 + qid;
                bf[jn][0] = f2tf(Bsb[(kb + qt) * NP + n0]);
                bf[jn][1] = f2tf(Bsb[(kb + qt + 4) * NP + n0]);
            }
#pragma unroll
            for (int im = 0; im < MF; im++)
#pragma unroll
                for (int jn = 0; jn < NF; jn++) {
                    asm volatile(
                        "mma.sync.aligned.m16n8k8.row.col.f32.tf32.tf32.f32 "
                        "{%0,%1,%2,%3}, {%4,%5,%6,%7}, {%8,%9}, {%0,%1,%2,%3};\n"
                        : "+f"(acc[im][jn][0]), "+f"(acc[im][jn][1]),
                          "+f"(acc[im][jn][2]), "+f"(acc[im][jn][3])
                        : "r"(af[im][0]), "r"(af[im][1]), "r"(af[im][2]), "r"(af[im][3]),
                          "r"(bf[jn][0]), "r"(bf[jn][1]));
                }
        }
        __syncthreads();
    }

#pragma unroll
    for (int im = 0; im < MF; im++) {
        int ra = row0 + warp_m * 32 + im * 16 + qid;
        int rb = ra + 8;
        float sa = 1.f, sb = 1.f;
        if (use_rowscale) {
            if (ra < N_NODES) sa = d_dinv[ra];
            if (rb < N_NODES) sb = d_dinv[rb];
        }
#pragma unroll
        for (int jn = 0; jn < NF; jn++) {
            int col = warp_n * WN + jn * 8 + qt * 2;
            float bx = 0.f, by = 0.f;
            if (bias) { bx = bias[col]; by = bias[col + 1]; }
            if (ra < N_NODES) {
                float2 o = make_float2(fmaf(acc[im][jn][0], sa, bx),
                                       fmaf(acc[im][jn][1], sa, by));
                *(float2*)&C[(size_t)ra * BN + col] = o;
            }
            if (rb < N_NODES) {
                float2 o = make_float2(fmaf(acc[im][jn][2], sb, bx),
                                       fmaf(acc[im][jn][3], sb, by));
                *(float2*)&C[(size_t)rb * BN + col] = o;
            }
        }
    }
}

// ---------------------------------------------------------------------------
// Aggregation: one warp per node, 4 independent float4 accumulators.
// ---------------------------------------------------------------------------
__global__ void agg_kernel(const float* __restrict__ bias) {
    int gw = (blockIdx.x * blockDim.x + threadIdx.x) >> 5;
    if (gw >= N_NODES) return;
    int lane = threadIdx.x & 31;
    int c = lane << 2;
    const float* __restrict__ g = (const float*)d_g;

    float4 a0 = *(const float4*)&g[(size_t)gw * C_FEAT + c];  // self loop
    float4 a1 = make_float4(0.f, 0.f, 0.f, 0.f);
    float4 a2 = a1, a3 = a1;

    int s = d_off[gw], e = d_off[gw + 1];
    for (int base = s; base < e; base += 32) {
        int m = e - base; if (m > 32) m = 32;
        int myu = (lane < m) ? d_adj[base + lane] : 0;
        int j = 0;
        for (; j + 4 <= m; j += 4) {
            int u0 = __shfl_sync(0xffffffffu, myu, j);
            int u1 = __shfl_sync(0xffffffffu, myu, j + 1);
            int u2 = __shfl_sync(0xffffffffu, myu, j + 2);
            int u3 = __shfl_sync(0xffffffffu, myu, j + 3);
            float4 t0 = *(const float4*)&g[(size_t)u0 * C_FEAT + c];
            float4 t1 = *(const float4*)&g[(size_t)u1 * C_FEAT + c];
            float4 t2 = *(const float4*)&g[(size_t)u2 * C_FEAT + c];
            float4 t3 = *(const float4*)&g[(size_t)u3 * C_FEAT + c];
            a0.x += t0.x; a0.y += t0.y; a0.z += t0.z; a0.w += t0.w;
            a1.x += t1.x; a1.y += t1.y; a1.z += t1.z; a1.w += t1.w;
            a2.x += t2.x; a2.y += t2.y; a2.z += t2.z; a2.w += t2.w;
            a3.x += t3.x; a3.y += t3.y; a3.z += t3.z; a3.w += t3.w;
        }
        for (; j < m; j++) {
            int u = __shfl_sync(0xffffffffu, myu, j);
            float4 t = *(const float4*)&g[(size_t)u * C_FEAT + c];
            a0.x += t.x; a0.y += t.y; a0.z += t.z; a0.w += t.w;
        }
    }
    float4 acc = make_float4(a0.x + a1.x + a2.x + a3.x,
                             a0.y + a1.y + a2.y + a3.y,
                             a0.z + a1.z + a2.z + a3.z,
                             a0.w + a1.w + a2.w + a3.w);
    float dv = d_dinv[gw];
    float4 bb = *(const float4*)&bias[c];
    float4 o;
    o.x = fmaxf(fmaf(acc.x, dv, bb.x), 0.f);
    o.y = fmaxf(fmaf(acc.y, dv, bb.y), 0.f);
    o.z = fmaxf(fmaf(acc.z, dv, bb.z), 0.f);
    o.w = fmaxf(fmaf(acc.w, dv, bb.w), 0.f);
    *(float4*)&d_y[(size_t)gw * C_FEAT + c] = o;
}

// ---------------------------------------------------------------------------
extern "C" void kernel_launch(void* const* d_in, const int* in_sizes, int n_in,
                              void* d_out, int out_size) {
    const float* x  = (const float*)d_in[0];
    const int*   ei = (const int*)d_in[1];     // int32
    const float* W1 = (const float*)d_in[2];
    const float* b1 = (const float*)d_in[3];
    const float* W2 = (const float*)d_in[4];
    const float* b2 = (const float*)d_in[5];
    const float* Wl = (const float*)d_in[6];
    const float* bl = (const float*)d_in[7];
    float* out = (float*)d_out;

    int E = in_sizes[1] / 2;   // 640000

    const int gemm_grid = (N_NODES + 63) / 64;          // 625
    const int agg_grid  = (N_NODES * 32 + 255) / 256;   // 5000

    // CSR build
    hist_kernel<<<(E / 4 + 255) / 256, 256>>>(ei, E);        // 0
    scan_kernel<<<1, 1024>>>();                              // 1
    scatter_kernel<<<(E / 4 + 255) / 256, 256>>>(ei, E);     // 2

    // Layer 1 (launch 3 = gemm1 -> ncu slot: validates occupancy change)
    gemm_tf32_kernel<128><<<gemm_grid, 256>>>(x, W1, nullptr, nullptr, 0, 1, 1);
    agg_kernel<<<agg_grid, 256>>>(b1);                       // 4
    // Layer 2
    gemm_tf32_kernel<128><<<gemm_grid, 256>>>(nullptr, W2, nullptr, nullptr, 1, 1, 1);
    agg_kernel<<<agg_grid, 256>>>(b2);                       // 6
    // Head
    gemm_tf32_kernel<64><<<gemm_grid, 256>>>(nullptr, Wl, bl, out, 1, 0, 0);
}